// round 1
// baseline (speedup 1.0000x reference)
#include <cuda_runtime.h>
#include <math.h>

// ---------------------------------------------------------------------------
// Problem constants
//   B=4, C=180, H=W=256, HEADS=6, hd=30, WS=16, PWS=8, HID=360
//   pixels M = B*H*W = 262144, HW = 65536
// ---------------------------------------------------------------------------
#define HW_   65536
#define M_    262144

// ---------------------------------------------------------------------------
// Scratch (static device globals — no allocation allowed)
// ---------------------------------------------------------------------------
__device__ float g_ymod[(size_t)M_ * 180];   // LN1+FiLM output (pixel-major, C fast); reused for attn output
__device__ float g_q   [(size_t)M_ * 180];   // q; reused for y2 (LN2 output)
__device__ float g_kv  [(size_t)M_ * 90];    // kv
__device__ float g_x1  [(size_t)M_ * 180];   // x + attn branch (pixel-major)
__device__ float g_u   [(size_t)M_ * 720];   // pin output
__device__ float g_g   [(size_t)M_ * 360];   // gated dwconv output
__device__ float g_kvm [4 * 360];            // FiLM params (attention branch)
__device__ float g_kvf [4 * 360];            // FiLM params (FFN branch)

// ---------------------------------------------------------------------------
// K0: kvm = k_v @ w_kern_attn^T ; kvf = k_v @ w_kern_ffn^T   (tiny)
// ---------------------------------------------------------------------------
__global__ void kvm_kernel(const float* __restrict__ k_v,
                           const float* __restrict__ wa,
                           const float* __restrict__ wf,
                           float* __restrict__ kvm, float* __restrict__ kvf)
{
    int b = blockIdx.x;
    __shared__ float ks[256];
    for (int i = threadIdx.x; i < 256; i += blockDim.x) ks[i] = k_v[b * 256 + i];
    __syncthreads();
    for (int o = threadIdx.x; o < 720; o += blockDim.x) {
        const float* wr = (o < 360) ? (wa + (size_t)o * 256) : (wf + (size_t)(o - 360) * 256);
        float s = 0.f;
        #pragma unroll 8
        for (int k = 0; k < 256; k++) s += ks[k] * wr[k];
        if (o < 360) kvm[b * 360 + o] = s;
        else         kvf[b * 360 + (o - 360)] = s;
    }
}

// ---------------------------------------------------------------------------
// K1: LN1 (over C of NCHW) + FiLM, output pixel-major (b,h,w,C)
//     block: 32 pixels x 8 channel-groups (256 threads)
// ---------------------------------------------------------------------------
__global__ void __launch_bounds__(256) ln1_kernel(
    const float* __restrict__ x, const float* __restrict__ lw,
    const float* __restrict__ lb, const float* __restrict__ kvm,
    float* __restrict__ out)
{
    __shared__ float buf[32][181];      // [pixel][channel], stride 181 (conflict-free)
    __shared__ float red[2][8][32];
    __shared__ float mean_s[32], rstd_s[32];
    __shared__ float prm[4][180];       // lnw, lnb, film scale, film shift

    int b  = blockIdx.y;
    int p0 = blockIdx.x * 32;
    int tid = threadIdx.x;
    int px = tid & 31, g = tid >> 5;

    for (int i = tid; i < 180; i += 256) {
        prm[0][i] = lw[i];
        prm[1][i] = lb[i];
        prm[2][i] = kvm[b * 360 + i];
        prm[3][i] = kvm[b * 360 + 180 + i];
    }

    const float* xb = x + (size_t)b * 180 * HW_ + p0 + px;
    float s = 0.f, ss = 0.f;
    for (int c = g; c < 180; c += 8) {
        float v = xb[(size_t)c * HW_];
        buf[px][c] = v;
        s += v; ss += v * v;
    }
    red[0][g][px] = s; red[1][g][px] = ss;
    __syncthreads();
    if (tid < 32) {
        float s2 = 0.f, ss2 = 0.f;
        #pragma unroll
        for (int gg = 0; gg < 8; gg++) { s2 += red[0][gg][tid]; ss2 += red[1][gg][tid]; }
        float mn  = s2 * (1.f / 180.f);
        float var = ss2 * (1.f / 180.f) - mn * mn;
        mean_s[tid] = mn;
        rstd_s[tid] = rsqrtf(var + 1e-5f);
    }
    __syncthreads();

    float* ob = out + ((size_t)b * HW_ + p0) * 180;
    for (int l = tid; l < 32 * 180; l += 256) {
        int p = l / 180, c = l - p * 180;
        float v = (buf[p][c] - mean_s[p]) * rstd_s[p] * prm[0][c] + prm[1][c];
        ob[l] = v * prm[2][c] + prm[3][c];
    }
}

// ---------------------------------------------------------------------------
// Generic NT GEMM:  C(MxN) = A(MxK) * W(NxK)^T  (+bias) (+epilogue)
//   128x128 tile, BK=32, 256 threads, 8x8 per thread.
//   EPI 0: C[m*N+n] = v
//   EPI 1: C[m*180+n] = v + ex_NCHW[b,n,p]            (proj + shortcut -> x1)
//   EPI 2: C_NCHW[b,n,p] = v + ex[m*180+n]            (pout + x1 -> final out)
// ---------------------------------------------------------------------------
template<int EPI>
__global__ void __launch_bounds__(256) gemm_nt(
    const float* __restrict__ A, const float* __restrict__ W,
    const float* __restrict__ bias, float* __restrict__ C,
    const float* __restrict__ ex, int N, int K)
{
    __shared__ float As[32][128];
    __shared__ float Ws[32][128];
    const int tid = threadIdx.x;
    const int m0 = blockIdx.y * 128;
    const int n0 = blockIdx.x * 128;
    const int tx = tid & 15, ty = tid >> 4;
    float acc[8][8];
    #pragma unroll
    for (int i = 0; i < 8; i++)
        #pragma unroll
        for (int j = 0; j < 8; j++) acc[i][j] = 0.f;

    for (int k0 = 0; k0 < K; k0 += 32) {
        #pragma unroll
        for (int i = 0; i < 16; i++) {
            int l = tid + i * 256;
            int kk = l & 31, mm = l >> 5;
            int k = k0 + kk;
            As[kk][mm] = (k < K) ? A[(size_t)(m0 + mm) * K + k] : 0.f;
        }
        #pragma unroll
        for (int i = 0; i < 16; i++) {
            int l = tid + i * 256;
            int kk = l & 31, nn = l >> 5;
            int k = k0 + kk;
            int n = n0 + nn;
            Ws[kk][nn] = (k < K && n < N) ? W[(size_t)n * K + k] : 0.f;
        }
        __syncthreads();
        #pragma unroll
        for (int kk = 0; kk < 32; kk++) {
            float a[8], bq[8];
            *(float4*)&a[0]  = *(const float4*)&As[kk][ty * 8];
            *(float4*)&a[4]  = *(const float4*)&As[kk][ty * 8 + 4];
            *(float4*)&bq[0] = *(const float4*)&Ws[kk][tx * 8];
            *(float4*)&bq[4] = *(const float4*)&Ws[kk][tx * 8 + 4];
            #pragma unroll
            for (int i = 0; i < 8; i++)
                #pragma unroll
                for (int j = 0; j < 8; j++)
                    acc[i][j] += a[i] * bq[j];
        }
        __syncthreads();
    }

    #pragma unroll
    for (int i = 0; i < 8; i++) {
        int m = m0 + ty * 8 + i;
        int b = m >> 16;         // / 65536
        int p = m & 65535;
        #pragma unroll
        for (int j = 0; j < 8; j++) {
            int n = n0 + tx * 8 + j;
            if (n < N) {
                float v = acc[i][j];
                if (bias) v += bias[n];
                if (EPI == 0) {
                    C[(size_t)m * N + n] = v;
                } else if (EPI == 1) {
                    v += ex[((size_t)b * 180 + n) * HW_ + p];
                    C[(size_t)m * 180 + n] = v;
                } else {
                    v += ex[(size_t)m * 180 + n];
                    C[((size_t)b * 180 + n) * HW_ + p] = v;
                }
            }
        }
    }
}

// ---------------------------------------------------------------------------
// K3: windowed attention.  One block per (window, head). 256 threads = 256
// query tokens. k/v are the permuted 2x2-merged kv (64 tokens x 30 dims).
// ---------------------------------------------------------------------------
__global__ void __launch_bounds__(256) attn_kernel(
    const float* __restrict__ q, const float* __restrict__ kv,
    const float* __restrict__ rel_table, float* __restrict__ out)
{
    int head = blockIdx.y;
    int win  = blockIdx.x;
    int b  = win >> 8;
    int wl = win & 255;
    int base_h = (wl >> 4) * 16;
    int base_w = (wl & 15) * 16;

    __shared__ float ks[64][30];
    __shared__ float vs[64][30];
    __shared__ float rel_s[225];
    int tid = threadIdx.x;

    for (int i = tid; i < 225; i += 256) rel_s[i] = rel_table[i * 6 + head];

    // gather permuted k/v for this head: token m=(i1,j1), dim e.
    // channel mapping: t = head*30+e ; i2=t/90, j2=(t%90)/45, d=t%45 ; kv chan = s*45+d
    for (int l = tid; l < 64 * 60; l += 256) {
        int m = l / 60; int r = l % 60; int s = r / 30; int e = r % 30;
        int t = head * 30 + e;
        int i2 = t / 90; int rr = t - i2 * 90; int j2 = rr / 45; int d = rr - j2 * 45;
        int py = base_h + ((m >> 3) << 1) + i2;
        int px = base_w + ((m & 7) << 1) + j2;
        size_t pix = (size_t)b * HW_ + py * 256 + px;
        float v = kv[pix * 90 + s * 45 + d];
        if (s == 0) ks[m][e] = v; else vs[m][e] = v;
    }
    __syncthreads();

    int n  = tid;
    int iy = n >> 4, ix = n & 15;
    size_t pixn = (size_t)b * HW_ + (base_h + iy) * 256 + base_w + ix;

    float qreg[30];
    #pragma unroll
    for (int e = 0; e < 30; e++) qreg[e] = q[pixn * 180 + head * 30 + e];

    const float scale = 0.1825741858350554f;   // 30^-0.5
    int qy = iy >> 1, qx = ix >> 1;

    float logit[64];
    float mx = -1e30f;
    #pragma unroll
    for (int m = 0; m < 64; m++) {
        float dot = 0.f;
        #pragma unroll
        for (int e = 0; e < 30; e++) dot += qreg[e] * ks[m][e];
        int dy = qy - (m >> 3) + 7;
        int dx = qx - (m & 7) + 7;
        float lg = dot * scale + rel_s[dy * 15 + dx];
        logit[m] = lg;
        mx = fmaxf(mx, lg);
    }
    float sum = 0.f;
    #pragma unroll
    for (int m = 0; m < 64; m++) {
        float p = __expf(logit[m] - mx);
        logit[m] = p;
        sum += p;
    }
    float inv = 1.0f / sum;
    float acc[30];
    #pragma unroll
    for (int e = 0; e < 30; e++) acc[e] = 0.f;
    #pragma unroll
    for (int m = 0; m < 64; m++) {
        float p = logit[m] * inv;
        #pragma unroll
        for (int e = 0; e < 30; e++) acc[e] += p * vs[m][e];
    }
    #pragma unroll
    for (int e = 0; e < 30; e++) out[pixn * 180 + head * 30 + e] = acc[e];
}

// ---------------------------------------------------------------------------
// K5: LN2 over pixel-major x1 + FiLM(kvf). One warp per pixel.
// ---------------------------------------------------------------------------
__global__ void __launch_bounds__(256) ln2_kernel(
    const float* __restrict__ x1, const float* __restrict__ lw,
    const float* __restrict__ lb, const float* __restrict__ kvf,
    float* __restrict__ out)
{
    int warp = threadIdx.x >> 5, lane = threadIdx.x & 31;
    size_t pix = (size_t)blockIdx.x * 8 + warp;
    int b = (int)(pix >> 16);
    const float* xp = x1 + pix * 180;

    float vals[6];
    float s = 0.f, ss = 0.f;
    #pragma unroll
    for (int i = 0; i < 6; i++) {
        int c = lane + i * 32;
        float v = (c < 180) ? xp[c] : 0.f;
        vals[i] = v; s += v; ss += v * v;
    }
    #pragma unroll
    for (int off = 16; off > 0; off >>= 1) {
        s  += __shfl_xor_sync(0xffffffffu, s,  off);
        ss += __shfl_xor_sync(0xffffffffu, ss, off);
    }
    float mean = s * (1.f / 180.f);
    float var  = ss * (1.f / 180.f) - mean * mean;
    float rstd = rsqrtf(var + 1e-5f);

    float* op = out + pix * 180;
    #pragma unroll
    for (int i = 0; i < 6; i++) {
        int c = lane + i * 32;
        if (c < 180) {
            float v = (vals[i] - mean) * rstd * lw[c] + lb[c];
            op[c] = v * kvf[b * 360 + c] + kvf[b * 360 + 180 + c];
        }
    }
}

// ---------------------------------------------------------------------------
// K7: depthwise 3x3 conv (pad 1) on 720 channels + exact-GELU gate.
//   g[:,c] = gelu(conv(u[:,c])) * conv(u[:,c+360]),  c in [0,360)
//   block: 8x8 pixel tile x 45 channels, smem-staged 10x10 halo tile.
// ---------------------------------------------------------------------------
__global__ void __launch_bounds__(360) dwconv_kernel(
    const float* __restrict__ u, const float* __restrict__ wdw,
    float* __restrict__ g)
{
    const int CC = 45;
    __shared__ float tile[10][10][CC];

    int chunk = blockIdx.z & 7;
    int b     = blockIdx.z >> 3;
    int c0 = chunk * CC;
    int h0 = blockIdx.y * 8, w0 = blockIdx.x * 8;
    int ch = threadIdx.x;        // 0..44
    int xcol = threadIdx.y;      // 0..7
    int tid = threadIdx.y * CC + threadIdx.x;

    float v1[8];
    #pragma unroll
    for (int half = 0; half < 2; half++) {
        int cbase = half * 360 + c0;
        __syncthreads();
        for (int l = tid; l < 100 * CC; l += 360) {
            int cc = l % CC; int pp = l / CC;
            int py = h0 + pp / 10 - 1;
            int px = w0 + pp % 10 - 1;
            float v = 0.f;
            if (py >= 0 && py < 256 && px >= 0 && px < 256)
                v = u[((size_t)b * HW_ + py * 256 + px) * 720 + cbase + cc];
            tile[pp / 10][pp % 10][cc] = v;
        }
        __syncthreads();
        float wreg[9];
        #pragma unroll
        for (int r = 0; r < 9; r++) wreg[r] = wdw[(size_t)(cbase + ch) * 9 + r];
        #pragma unroll
        for (int oy = 0; oy < 8; oy++) {
            float a = 0.f;
            #pragma unroll
            for (int ky = 0; ky < 3; ky++)
                #pragma unroll
                for (int kx = 0; kx < 3; kx++)
                    a += tile[oy + ky][xcol + kx][ch] * wreg[ky * 3 + kx];
            if (half == 0) {
                v1[oy] = a;
            } else {
                float g1 = v1[oy];
                float gl = 0.5f * g1 * (1.f + erff(g1 * 0.70710678118654752f));
                g[((size_t)b * HW_ + (h0 + oy) * 256 + w0 + xcol) * 360 + c0 + ch] = gl * a;
            }
        }
    }
}

// ---------------------------------------------------------------------------
// Launch sequence (graph-capturable, allocation-free)
// ---------------------------------------------------------------------------
extern "C" void kernel_launch(void* const* d_in, const int* in_sizes, int n_in,
                              void* d_out, int out_size)
{
    const float* x           = (const float*)d_in[0];
    const float* k_v         = (const float*)d_in[1];
    const float* ln1_w       = (const float*)d_in[2];
    const float* ln1_b       = (const float*)d_in[3];
    const float* ln2_w       = (const float*)d_in[4];
    const float* ln2_b       = (const float*)d_in[5];
    const float* w_kern_attn = (const float*)d_in[6];
    const float* rel_table   = (const float*)d_in[7];
    const float* w_kv        = (const float*)d_in[8];
    const float* b_kv        = (const float*)d_in[9];
    const float* w_q         = (const float*)d_in[10];
    const float* b_q         = (const float*)d_in[11];
    const float* w_proj      = (const float*)d_in[12];
    const float* b_proj      = (const float*)d_in[13];
    const float* w_kern_ffn  = (const float*)d_in[14];
    const float* w_pin       = (const float*)d_in[15];
    const float* w_dw        = (const float*)d_in[16];
    const float* w_pout      = (const float*)d_in[17];
    float* out = (float*)d_out;

    float *ymod, *q, *kv, *x1, *u, *gg, *kvm, *kvf;
    cudaGetSymbolAddress((void**)&ymod, g_ymod);
    cudaGetSymbolAddress((void**)&q,    g_q);
    cudaGetSymbolAddress((void**)&kv,   g_kv);
    cudaGetSymbolAddress((void**)&x1,   g_x1);
    cudaGetSymbolAddress((void**)&u,    g_u);
    cudaGetSymbolAddress((void**)&gg,   g_g);
    cudaGetSymbolAddress((void**)&kvm,  g_kvm);
    cudaGetSymbolAddress((void**)&kvf,  g_kvf);

    // K0: FiLM kernels
    kvm_kernel<<<4, 256>>>(k_v, w_kern_attn, w_kern_ffn, kvm, kvf);
    // K1: LN1 + FiLM -> ymod (pixel-major)
    ln1_kernel<<<dim3(2048, 4), 256>>>(x, ln1_w, ln1_b, kvm, ymod);
    // K2: q and kv projections
    gemm_nt<0><<<dim3(2, 2048), 256>>>(ymod, w_q,  b_q,  q,  nullptr, 180, 180);
    gemm_nt<0><<<dim3(1, 2048), 256>>>(ymod, w_kv, b_kv, kv, nullptr,  90, 180);
    // K3: windowed attention (writes into ymod, which is now dead)
    attn_kernel<<<dim3(1024, 6), 256>>>(q, kv, rel_table, ymod);
    // K4: proj + shortcut (x, NCHW) -> x1 (pixel-major)
    gemm_nt<1><<<dim3(2, 2048), 256>>>(ymod, w_proj, b_proj, x1, x, 180, 180);
    // K5: LN2 + FiLM -> y2 (reuse q buffer)
    ln2_kernel<<<32768, 256>>>(x1, ln2_w, ln2_b, kvf, q);
    // K6: pin (180 -> 720), no bias
    gemm_nt<0><<<dim3(6, 2048), 256>>>(q, w_pin, nullptr, u, nullptr, 720, 180);
    // K7: depthwise conv + GELU gate -> gg (360 ch)
    dwconv_kernel<<<dim3(32, 32, 32), dim3(45, 8)>>>(u, w_dw, gg);
    // K8: pout (360 -> 180) + x1, write final NCHW output
    gemm_nt<2><<<dim3(2, 2048), 256>>>(gg, w_pout, nullptr, out, x1, 180, 360);
}

// round 2
// speedup vs baseline: 2.5438x; 2.5438x over previous
#include <cuda_runtime.h>
#include <math.h>
#include <stdint.h>

// ---------------------------------------------------------------------------
// Problem constants
//   B=4, C=180, H=W=256, HEADS=6, hd=30, WS=16, PWS=8, HID=360
// ---------------------------------------------------------------------------
#define HW_   65536
#define M_    262144

// ---------------------------------------------------------------------------
// Scratch (static device globals — no allocation allowed)
// ---------------------------------------------------------------------------
__device__ float g_ymod[(size_t)M_ * 180];   // LN1+FiLM out; reused for attn out
__device__ float g_q   [(size_t)M_ * 180];   // q; reused for LN2 out
__device__ float g_kv  [(size_t)M_ * 90];
__device__ float g_x1  [(size_t)M_ * 180];   // x + attn branch (pixel-major)
__device__ float g_u   [(size_t)M_ * 720];
__device__ float g_g   [(size_t)M_ * 360];
__device__ float g_kvm [4 * 360];
__device__ float g_kvf [4 * 360];

// ---------------------------------------------------------------------------
// K0: FiLM kernels (tiny)
// ---------------------------------------------------------------------------
__global__ void kvm_kernel(const float* __restrict__ k_v,
                           const float* __restrict__ wa,
                           const float* __restrict__ wf,
                           float* __restrict__ kvm, float* __restrict__ kvf)
{
    int b = blockIdx.x;
    __shared__ float ks[256];
    for (int i = threadIdx.x; i < 256; i += blockDim.x) ks[i] = k_v[b * 256 + i];
    __syncthreads();
    for (int o = threadIdx.x; o < 720; o += blockDim.x) {
        const float* wr = (o < 360) ? (wa + (size_t)o * 256) : (wf + (size_t)(o - 360) * 256);
        float s = 0.f;
        #pragma unroll 8
        for (int k = 0; k < 256; k++) s += ks[k] * wr[k];
        if (o < 360) kvm[b * 360 + o] = s;
        else         kvf[b * 360 + (o - 360)] = s;
    }
}

// ---------------------------------------------------------------------------
// K1: LN1 over C of NCHW + FiLM, output pixel-major
// ---------------------------------------------------------------------------
__global__ void __launch_bounds__(256) ln1_kernel(
    const float* __restrict__ x, const float* __restrict__ lw,
    const float* __restrict__ lb, const float* __restrict__ kvm,
    float* __restrict__ out)
{
    __shared__ float buf[32][181];
    __shared__ float red[2][8][32];
    __shared__ float mean_s[32], rstd_s[32];
    __shared__ float prm[4][180];

    int b  = blockIdx.y;
    int p0 = blockIdx.x * 32;
    int tid = threadIdx.x;
    int px = tid & 31, g = tid >> 5;

    for (int i = tid; i < 180; i += 256) {
        prm[0][i] = lw[i];
        prm[1][i] = lb[i];
        prm[2][i] = kvm[b * 360 + i];
        prm[3][i] = kvm[b * 360 + 180 + i];
    }

    const float* xb = x + (size_t)b * 180 * HW_ + p0 + px;
    float s = 0.f, ss = 0.f;
    for (int c = g; c < 180; c += 8) {
        float v = xb[(size_t)c * HW_];
        buf[px][c] = v;
        s += v; ss += v * v;
    }
    red[0][g][px] = s; red[1][g][px] = ss;
    __syncthreads();
    if (tid < 32) {
        float s2 = 0.f, ss2 = 0.f;
        #pragma unroll
        for (int gg = 0; gg < 8; gg++) { s2 += red[0][gg][tid]; ss2 += red[1][gg][tid]; }
        float mn  = s2 * (1.f / 180.f);
        float var = ss2 * (1.f / 180.f) - mn * mn;
        mean_s[tid] = mn;
        rstd_s[tid] = rsqrtf(var + 1e-5f);
    }
    __syncthreads();

    float* ob = out + ((size_t)b * HW_ + p0) * 180;
    for (int l = tid; l < 32 * 180; l += 256) {
        int p = l / 180, c = l - p * 180;
        float v = (buf[p][c] - mean_s[p]) * rstd_s[p] * prm[0][c] + prm[1][c];
        ob[l] = v * prm[2][c] + prm[3][c];
    }
}

// ---------------------------------------------------------------------------
// TF32 tensor-core GEMM:  C(MxN) = A(MxK) * W(NxK)^T  (+bias)(+epilogue)
//   128x128 tile, BK=32, 256 threads, 8 warps (2m x 4n), warp tile 64x32,
//   mma.sync.m16n8k8 tf32. Permuted smem ([row][k%4][k/4], row stride 36
//   floats) so each fragment pair (2 k-steps) is one conflict-free LDS.128.
//   Register-staged double buffering hides global latency.
//   EPI 0: C[m*N+n] = v
//   EPI 1: C[m*180+n] = v + ex_NCHW[b,n,p]     (proj + shortcut)
//   EPI 2: C_NCHW[b,n,p] = v + ex[m*180+n]     (pout + x1 -> out)
// ---------------------------------------------------------------------------
__device__ __forceinline__ uint32_t f2tf(float f) {
    uint32_t r;
    asm("cvt.rna.tf32.f32 %0, %1;" : "=r"(r) : "f"(f));
    return r;
}
__device__ __forceinline__ void mma8(float* d,
    uint32_t a0, uint32_t a1, uint32_t a2, uint32_t a3,
    uint32_t b0, uint32_t b1)
{
    asm volatile(
        "mma.sync.aligned.m16n8k8.row.col.f32.tf32.tf32.f32 "
        "{%0,%1,%2,%3},{%4,%5,%6,%7},{%8,%9},{%0,%1,%2,%3};"
        : "+f"(d[0]), "+f"(d[1]), "+f"(d[2]), "+f"(d[3])
        : "r"(a0), "r"(a1), "r"(a2), "r"(a3), "r"(b0), "r"(b1));
}

#define SMB (128 * 36)          // one operand buffer, in uint32

template<int EPI>
__global__ void __launch_bounds__(256, 1) gemm_tf32(
    const float* __restrict__ A, const float* __restrict__ W,
    const float* __restrict__ bias, float* __restrict__ C,
    const float* __restrict__ ex, int N, int K)
{
    extern __shared__ uint32_t dynsm[];   // [2][A(SMB) + W(SMB)]
    const int tid  = threadIdx.x;
    const int m0   = blockIdx.y * 128;
    const int n0   = blockIdx.x * 128;
    const int lane = tid & 31;
    const int wid  = tid >> 5;
    const int g    = lane >> 2, t4 = lane & 3;
    const int wm   = wid & 1;            // 0..1 : 64-row slab
    const int wn   = wid >> 1;           // 0..3 : 32-col slab

    float acc[4][4][4];
    #pragma unroll
    for (int i = 0; i < 4; i++)
        #pragma unroll
        for (int j = 0; j < 4; j++)
            #pragma unroll
            for (int e = 0; e < 4; e++) acc[i][j][e] = 0.f;

    const int nkt = (K + 31) / 32;

    float4 ra[4], rw[4];

    // --- fetch helpers (LDG into regs) ---
    auto fetchA = [&](int k0) {
        #pragma unroll
        for (int i = 0; i < 4; i++) {
            int l = tid + i * 256;
            int mm = l >> 3, j = l & 7;
            int k = k0 + j * 4;
            const float* p = A + (size_t)(m0 + mm) * K + k;
            float4 v;
            if (k + 3 < K) {
                v = *(const float4*)p;
            } else {
                v.x = (k     < K) ? p[0] : 0.f;
                v.y = (k + 1 < K) ? p[1] : 0.f;
                v.z = (k + 2 < K) ? p[2] : 0.f;
                v.w = (k + 3 < K) ? p[3] : 0.f;
            }
            ra[i] = v;
        }
    };
    auto fetchW = [&](int k0) {
        #pragma unroll
        for (int i = 0; i < 4; i++) {
            int l = tid + i * 256;
            int nn = l >> 3, j = l & 7;
            int k = k0 + j * 4;
            int n = n0 + nn;
            float4 v = make_float4(0.f, 0.f, 0.f, 0.f);
            if (n < N) {
                const float* p = W + (size_t)n * K + k;
                if (k + 3 < K) {
                    v = *(const float4*)p;
                } else {
                    v.x = (k     < K) ? p[0] : 0.f;
                    v.y = (k + 1 < K) ? p[1] : 0.f;
                    v.z = (k + 2 < K) ? p[2] : 0.f;
                    v.w = (k + 3 < K) ? p[3] : 0.f;
                }
            }
            rw[i] = v;
        }
    };
    auto stage = [&](uint32_t* As, uint32_t* Ws) {
        #pragma unroll
        for (int i = 0; i < 4; i++) {
            int l = tid + i * 256;
            int mm = l >> 3, j = l & 7;
            uint32_t* da = As + mm * 36 + j;
            da[0]  = f2tf(ra[i].x);
            da[8]  = f2tf(ra[i].y);
            da[16] = f2tf(ra[i].z);
            da[24] = f2tf(ra[i].w);
            uint32_t* dw = Ws + mm * 36 + j;   // mm == nn here
            dw[0]  = f2tf(rw[i].x);
            dw[8]  = f2tf(rw[i].y);
            dw[16] = f2tf(rw[i].z);
            dw[24] = f2tf(rw[i].w);
        }
    };

    // prologue: tile 0
    fetchA(0); fetchW(0);
    stage(dynsm, dynsm + SMB);
    __syncthreads();

    for (int kt = 0; kt < nkt; kt++) {
        uint32_t* As = dynsm + (kt & 1) * (2 * SMB);
        uint32_t* Ws = As + SMB;

        if (kt + 1 < nkt) { fetchA((kt + 1) * 32); fetchW((kt + 1) * 32); }

        const uint4* As4 = (const uint4*)As;
        const uint4* Ws4 = (const uint4*)Ws;
        #pragma unroll
        for (int h = 0; h < 2; h++) {
            uint4 af0[4], af1[4], bf[4];
            #pragma unroll
            for (int mt = 0; mt < 4; mt++) {
                int r = wm * 64 + mt * 16 + g;
                af0[mt] = As4[r * 9 + t4 * 2 + h];
                af1[mt] = As4[(r + 8) * 9 + t4 * 2 + h];
            }
            #pragma unroll
            for (int nt = 0; nt < 4; nt++) {
                int n = wn * 32 + nt * 8 + g;
                bf[nt] = Ws4[n * 9 + t4 * 2 + h];
            }
            #pragma unroll
            for (int mt = 0; mt < 4; mt++)
                #pragma unroll
                for (int nt = 0; nt < 4; nt++) {
                    mma8(acc[mt][nt], af0[mt].x, af1[mt].x, af0[mt].y, af1[mt].y,
                         bf[nt].x, bf[nt].y);
                    mma8(acc[mt][nt], af0[mt].z, af1[mt].z, af0[mt].w, af1[mt].w,
                         bf[nt].z, bf[nt].w);
                }
        }

        if (kt + 1 < nkt) {
            uint32_t* As2 = dynsm + ((kt + 1) & 1) * (2 * SMB);
            stage(As2, As2 + SMB);
        }
        __syncthreads();
    }

    // epilogue
    #pragma unroll
    for (int mt = 0; mt < 4; mt++) {
        #pragma unroll
        for (int rr = 0; rr < 2; rr++) {
            int m = m0 + wm * 64 + mt * 16 + g + rr * 8;
            int b = m >> 16;
            int p = m & 65535;
            #pragma unroll
            for (int nt = 0; nt < 4; nt++) {
                #pragma unroll
                for (int cc = 0; cc < 2; cc++) {
                    int n = n0 + wn * 32 + nt * 8 + t4 * 2 + cc;
                    if (n < N) {
                        float v = acc[mt][nt][rr * 2 + cc];
                        if (bias) v += bias[n];
                        if (EPI == 0) {
                            C[(size_t)m * N + n] = v;
                        } else if (EPI == 1) {
                            v += ex[((size_t)b * 180 + n) * HW_ + p];
                            C[(size_t)m * 180 + n] = v;
                        } else {
                            v += ex[(size_t)m * 180 + n];
                            C[((size_t)b * 180 + n) * HW_ + p] = v;
                        }
                    }
                }
            }
        }
    }
}

// ---------------------------------------------------------------------------
// K3: windowed attention. One block per (window, head), 256 query tokens.
// ---------------------------------------------------------------------------
__global__ void __launch_bounds__(256) attn_kernel(
    const float* __restrict__ q, const float* __restrict__ kv,
    const float* __restrict__ rel_table, float* __restrict__ out)
{
    int head = blockIdx.y;
    int win  = blockIdx.x;
    int b  = win >> 8;
    int wl = win & 255;
    int base_h = (wl >> 4) * 16;
    int base_w = (wl & 15) * 16;

    __shared__ float ks[64][30];
    __shared__ float vs[64][30];
    __shared__ float rel_s[225];
    int tid = threadIdx.x;

    for (int i = tid; i < 225; i += 256) rel_s[i] = rel_table[i * 6 + head];

    for (int l = tid; l < 64 * 60; l += 256) {
        int m = l / 60; int r = l % 60; int s = r / 30; int e = r % 30;
        int t = head * 30 + e;
        int i2 = t / 90; int rr = t - i2 * 90; int j2 = rr / 45; int d = rr - j2 * 45;
        int py = base_h + ((m >> 3) << 1) + i2;
        int px = base_w + ((m & 7) << 1) + j2;
        size_t pix = (size_t)b * HW_ + py * 256 + px;
        float v = kv[pix * 90 + s * 45 + d];
        if (s == 0) ks[m][e] = v; else vs[m][e] = v;
    }
    __syncthreads();

    int n  = tid;
    int iy = n >> 4, ix = n & 15;
    size_t pixn = (size_t)b * HW_ + (base_h + iy) * 256 + base_w + ix;

    float qreg[30];
    #pragma unroll
    for (int e = 0; e < 30; e++) qreg[e] = q[pixn * 180 + head * 30 + e];

    const float scale = 0.1825741858350554f;   // 30^-0.5
    int qy = iy >> 1, qx = ix >> 1;

    float logit[64];
    float mx = -1e30f;
    #pragma unroll
    for (int m = 0; m < 64; m++) {
        float dot = 0.f;
        #pragma unroll
        for (int e = 0; e < 30; e++) dot += qreg[e] * ks[m][e];
        int dy = qy - (m >> 3) + 7;
        int dx = qx - (m & 7) + 7;
        float lg = dot * scale + rel_s[dy * 15 + dx];
        logit[m] = lg;
        mx = fmaxf(mx, lg);
    }
    float sum = 0.f;
    #pragma unroll
    for (int m = 0; m < 64; m++) {
        float p = __expf(logit[m] - mx);
        logit[m] = p;
        sum += p;
    }
    float inv = 1.0f / sum;
    float acc[30];
    #pragma unroll
    for (int e = 0; e < 30; e++) acc[e] = 0.f;
    #pragma unroll
    for (int m = 0; m < 64; m++) {
        float p = logit[m] * inv;
        #pragma unroll
        for (int e = 0; e < 30; e++) acc[e] += p * vs[m][e];
    }
    #pragma unroll
    for (int e = 0; e < 30; e++) out[pixn * 180 + head * 30 + e] = acc[e];
}

// ---------------------------------------------------------------------------
// K5: LN2 over pixel-major x1 + FiLM. One warp per pixel.
// ---------------------------------------------------------------------------
__global__ void __launch_bounds__(256) ln2_kernel(
    const float* __restrict__ x1, const float* __restrict__ lw,
    const float* __restrict__ lb, const float* __restrict__ kvf,
    float* __restrict__ out)
{
    int warp = threadIdx.x >> 5, lane = threadIdx.x & 31;
    size_t pix = (size_t)blockIdx.x * 8 + warp;
    int b = (int)(pix >> 16);
    const float* xp = x1 + pix * 180;

    float vals[6];
    float s = 0.f, ss = 0.f;
    #pragma unroll
    for (int i = 0; i < 6; i++) {
        int c = lane + i * 32;
        float v = (c < 180) ? xp[c] : 0.f;
        vals[i] = v; s += v; ss += v * v;
    }
    #pragma unroll
    for (int off = 16; off > 0; off >>= 1) {
        s  += __shfl_xor_sync(0xffffffffu, s,  off);
        ss += __shfl_xor_sync(0xffffffffu, ss, off);
    }
    float mean = s * (1.f / 180.f);
    float var  = ss * (1.f / 180.f) - mean * mean;
    float rstd = rsqrtf(var + 1e-5f);

    float* op = out + pix * 180;
    #pragma unroll
    for (int i = 0; i < 6; i++) {
        int c = lane + i * 32;
        if (c < 180) {
            float v = (vals[i] - mean) * rstd * lw[c] + lb[c];
            op[c] = v * kvf[b * 360 + c] + kvf[b * 360 + 180 + c];
        }
    }
}

// ---------------------------------------------------------------------------
// K7: depthwise 3x3 + exact-GELU gate
// ---------------------------------------------------------------------------
__global__ void __launch_bounds__(360) dwconv_kernel(
    const float* __restrict__ u, const float* __restrict__ wdw,
    float* __restrict__ g)
{
    const int CC = 45;
    __shared__ float tile[10][10][CC];

    int chunk = blockIdx.z & 7;
    int b     = blockIdx.z >> 3;
    int c0 = chunk * CC;
    int h0 = blockIdx.y * 8, w0 = blockIdx.x * 8;
    int ch = threadIdx.x;
    int xcol = threadIdx.y;
    int tid = threadIdx.y * CC + threadIdx.x;

    float v1[8];
    #pragma unroll
    for (int half = 0; half < 2; half++) {
        int cbase = half * 360 + c0;
        __syncthreads();
        for (int l = tid; l < 100 * CC; l += 360) {
            int cc = l % CC; int pp = l / CC;
            int py = h0 + pp / 10 - 1;
            int px = w0 + pp % 10 - 1;
            float v = 0.f;
            if (py >= 0 && py < 256 && px >= 0 && px < 256)
                v = u[((size_t)b * HW_ + py * 256 + px) * 720 + cbase + cc];
            tile[pp / 10][pp % 10][cc] = v;
        }
        __syncthreads();
        float wreg[9];
        #pragma unroll
        for (int r = 0; r < 9; r++) wreg[r] = wdw[(size_t)(cbase + ch) * 9 + r];
        #pragma unroll
        for (int oy = 0; oy < 8; oy++) {
            float a = 0.f;
            #pragma unroll
            for (int ky = 0; ky < 3; ky++)
                #pragma unroll
                for (int kx = 0; kx < 3; kx++)
                    a += tile[oy + ky][xcol + kx][ch] * wreg[ky * 3 + kx];
            if (half == 0) {
                v1[oy] = a;
            } else {
                float g1 = v1[oy];
                float gl = 0.5f * g1 * (1.f + erff(g1 * 0.70710678118654752f));
                g[((size_t)b * HW_ + (h0 + oy) * 256 + w0 + xcol) * 360 + c0 + ch] = gl * a;
            }
        }
    }
}

// ---------------------------------------------------------------------------
// Launch sequence
// ---------------------------------------------------------------------------
extern "C" void kernel_launch(void* const* d_in, const int* in_sizes, int n_in,
                              void* d_out, int out_size)
{
    const float* x           = (const float*)d_in[0];
    const float* k_v         = (const float*)d_in[1];
    const float* ln1_w       = (const float*)d_in[2];
    const float* ln1_b       = (const float*)d_in[3];
    const float* ln2_w       = (const float*)d_in[4];
    const float* ln2_b       = (const float*)d_in[5];
    const float* w_kern_attn = (const float*)d_in[6];
    const float* rel_table   = (const float*)d_in[7];
    const float* w_kv        = (const float*)d_in[8];
    const float* b_kv        = (const float*)d_in[9];
    const float* w_q         = (const float*)d_in[10];
    const float* b_q         = (const float*)d_in[11];
    const float* w_proj      = (const float*)d_in[12];
    const float* b_proj      = (const float*)d_in[13];
    const float* w_kern_ffn  = (const float*)d_in[14];
    const float* w_pin       = (const float*)d_in[15];
    const float* w_dw        = (const float*)d_in[16];
    const float* w_pout      = (const float*)d_in[17];
    float* out = (float*)d_out;

    float *ymod, *q, *kv, *x1, *u, *gg, *kvm, *kvf;
    cudaGetSymbolAddress((void**)&ymod, g_ymod);
    cudaGetSymbolAddress((void**)&q,    g_q);
    cudaGetSymbolAddress((void**)&kv,   g_kv);
    cudaGetSymbolAddress((void**)&x1,   g_x1);
    cudaGetSymbolAddress((void**)&u,    g_u);
    cudaGetSymbolAddress((void**)&gg,   g_g);
    cudaGetSymbolAddress((void**)&kvm,  g_kvm);
    cudaGetSymbolAddress((void**)&kvf,  g_kvf);

    const int SMEM = 4 * SMB * sizeof(uint32_t);   // 73728 B (double-buffered)
    cudaFuncSetAttribute(gemm_tf32<0>, cudaFuncAttributeMaxDynamicSharedMemorySize, SMEM);
    cudaFuncSetAttribute(gemm_tf32<1>, cudaFuncAttributeMaxDynamicSharedMemorySize, SMEM);
    cudaFuncSetAttribute(gemm_tf32<2>, cudaFuncAttributeMaxDynamicSharedMemorySize, SMEM);

    // K0: FiLM params
    kvm_kernel<<<4, 256>>>(k_v, w_kern_attn, w_kern_ffn, kvm, kvf);
    // K1: LN1 + FiLM -> ymod (pixel-major)
    ln1_kernel<<<dim3(2048, 4), 256>>>(x, ln1_w, ln1_b, kvm, ymod);
    // K2: q and kv projections (tf32 TC)
    gemm_tf32<0><<<dim3(2, 2048), 256, SMEM>>>(ymod, w_q,  b_q,  q,  nullptr, 180, 180);
    gemm_tf32<0><<<dim3(1, 2048), 256, SMEM>>>(ymod, w_kv, b_kv, kv, nullptr,  90, 180);
    // K3: windowed attention (writes into ymod, now dead)
    attn_kernel<<<dim3(1024, 6), 256>>>(q, kv, rel_table, ymod);
    // K4: proj + shortcut -> x1
    gemm_tf32<1><<<dim3(2, 2048), 256, SMEM>>>(ymod, w_proj, b_proj, x1, x, 180, 180);
    // K5: LN2 + FiLM (reuse q buffer)
    ln2_kernel<<<32768, 256>>>(x1, ln2_w, ln2_b, kvf, q);
    // K6: pin (180 -> 720)
    gemm_tf32<0><<<dim3(6, 2048), 256, SMEM>>>(q, w_pin, nullptr, u, nullptr, 720, 180);
    // K7: depthwise conv + GELU gate
    dwconv_kernel<<<dim3(32, 32, 32), dim3(45, 8)>>>(u, w_dw, gg);
    // K8: pout (360 -> 180) + x1 -> final NCHW out
    gemm_tf32<2><<<dim3(2, 2048), 256, SMEM>>>(gg, w_pout, nullptr, out, x1, 180, 360);
}

// round 4
// speedup vs baseline: 4.6120x; 1.8130x over previous
#include <cuda_runtime.h>
#include <cuda_bf16.h>
#include <math.h>
#include <stdint.h>

// ---------------------------------------------------------------------------
// B=4, C=180, H=W=256, HEADS=6, hd=30, WS=16, PWS=8, HID=360
// ---------------------------------------------------------------------------
#define HW_   65536
#define M_    262144

typedef __nv_bfloat16 bf16;

// ---------------------------------------------------------------------------
// Scratch
// ---------------------------------------------------------------------------
__device__ bf16  g_ymod[(size_t)M_ * 192];   // LN1+FiLM out / attn out (pad ch 180..191 = 0)
__device__ bf16  g_qb  [(size_t)M_ * 192];   // q (stride 192)
__device__ bf16  g_kvb [(size_t)M_ * 90];    // kv (stride 90)
__device__ float g_x1  [(size_t)M_ * 180];   // residual trunk after attn (fp32)
__device__ bf16  g_y2  [(size_t)M_ * 192];   // LN2+FiLM out
__device__ bf16  g_u   [(size_t)M_ * 768];   // pin out (pad 720..767 = 0)
__device__ bf16  g_gt  [(size_t)M_ * 384];   // gated dwconv out (pad 360..383 = 0)
__device__ float g_kvm [4 * 360];
__device__ float g_kvf [4 * 360];
// bf16 weights, K zero-padded
__device__ bf16  g_wq   [180 * 192];
__device__ bf16  g_wkv  [ 90 * 192];
__device__ bf16  g_wproj[180 * 192];
__device__ bf16  g_wpin [720 * 192];
__device__ bf16  g_wpout[180 * 384];

// ---------------------------------------------------------------------------
// Weight conversion fp32[N][K] -> bf16[N][KP] (zero-padded K)
// ---------------------------------------------------------------------------
__global__ void wconv_kernel(const float* __restrict__ src, bf16* __restrict__ dst,
                             int NN, int K, int KP)
{
    int i = blockIdx.x * 256 + threadIdx.x;
    if (i < NN * KP) {
        int n = i / KP, k = i - n * KP;
        dst[i] = __float2bfloat16(k < K ? src[(size_t)n * K + k] : 0.f);
    }
}

// ---------------------------------------------------------------------------
// FiLM params
// ---------------------------------------------------------------------------
__global__ void kvm_kernel(const float* __restrict__ k_v,
                           const float* __restrict__ wa,
                           const float* __restrict__ wf,
                           float* __restrict__ kvm, float* __restrict__ kvf)
{
    int b = blockIdx.x;
    __shared__ float ks[256];
    for (int i = threadIdx.x; i < 256; i += blockDim.x) ks[i] = k_v[b * 256 + i];
    __syncthreads();
    for (int o = threadIdx.x; o < 720; o += blockDim.x) {
        const float* wr = (o < 360) ? (wa + (size_t)o * 256) : (wf + (size_t)(o - 360) * 256);
        float s = 0.f;
        #pragma unroll 8
        for (int k = 0; k < 256; k++) s += ks[k] * wr[k];
        if (o < 360) kvm[b * 360 + o] = s;
        else         kvf[b * 360 + (o - 360)] = s;
    }
}

// ---------------------------------------------------------------------------
// LN1 over C of NCHW + FiLM -> bf16 pixel-major stride 192 (pad zeros)
// ---------------------------------------------------------------------------
__global__ void __launch_bounds__(256) ln1_kernel(
    const float* __restrict__ x, const float* __restrict__ lw,
    const float* __restrict__ lb, const float* __restrict__ kvm,
    bf16* __restrict__ out)
{
    __shared__ float buf[32][181];
    __shared__ float red[2][8][32];
    __shared__ float mean_s[32], rstd_s[32];
    __shared__ float prm[4][180];

    int b  = blockIdx.y;
    int p0 = blockIdx.x * 32;
    int tid = threadIdx.x;
    int px = tid & 31, g = tid >> 5;

    for (int i = tid; i < 180; i += 256) {
        prm[0][i] = lw[i];
        prm[1][i] = lb[i];
        prm[2][i] = kvm[b * 360 + i];
        prm[3][i] = kvm[b * 360 + 180 + i];
    }

    const float* xb = x + (size_t)b * 180 * HW_ + p0 + px;
    float s = 0.f, ss = 0.f;
    for (int c = g; c < 180; c += 8) {
        float v = xb[(size_t)c * HW_];
        buf[px][c] = v;
        s += v; ss += v * v;
    }
    red[0][g][px] = s; red[1][g][px] = ss;
    __syncthreads();
    if (tid < 32) {
        float s2 = 0.f, ss2 = 0.f;
        #pragma unroll
        for (int gg = 0; gg < 8; gg++) { s2 += red[0][gg][tid]; ss2 += red[1][gg][tid]; }
        float mn  = s2 * (1.f / 180.f);
        float var = ss2 * (1.f / 180.f) - mn * mn;
        mean_s[tid] = mn;
        rstd_s[tid] = rsqrtf(var + 1e-5f);
    }
    __syncthreads();

    __nv_bfloat162* ob = (__nv_bfloat162*)(out + ((size_t)b * HW_ + p0) * 192);
    for (int l = tid; l < 32 * 96; l += 256) {
        int p = l / 96, c2 = (l - p * 96) * 2;
        float v0 = 0.f, v1 = 0.f;
        if (c2 < 180) {
            v0 = (buf[p][c2] - mean_s[p]) * rstd_s[p] * prm[0][c2] + prm[1][c2];
            v0 = v0 * prm[2][c2] + prm[3][c2];
            int c3 = c2 + 1;
            v1 = (buf[p][c3] - mean_s[p]) * rstd_s[p] * prm[0][c3] + prm[1][c3];
            v1 = v1 * prm[2][c3] + prm[3][c3];
        }
        ob[p * 96 + (c2 >> 1)] = __floats2bfloat162_rn(v0, v1);
    }
}

// ---------------------------------------------------------------------------
// bf16 tensor-core GEMM: C(MxN) = A(MxKP) * W(NxKP)^T (+bias)(+epilogue)
//   128x128 tile, BK=32, 256 thr, 8 warps (2m x 4n), warp tile 64x32,
//   mma.m16n8k16, cp.async 3-stage, ldmatrix, XOR-swizzled smem.
//   EPI 0: bf16 out stride NP, zero for n in [N,NP)
//   EPI 1: fp32 out stride 180 = v + ex_NCHW[b,n,p]
//   EPI 2: fp32 NCHW out = v + ex[m*180+n]
// ---------------------------------------------------------------------------
__device__ __forceinline__ void cpa16(uint32_t dst, const void* src, int sz) {
    asm volatile("cp.async.cg.shared.global [%0], [%1], 16, %2;"
                 :: "r"(dst), "l"(src), "r"(sz));
}
__device__ __forceinline__ void mma_bf16(float* d, const uint32_t* a, const uint32_t* b) {
    asm volatile(
        "mma.sync.aligned.m16n8k16.row.col.f32.bf16.bf16.f32 "
        "{%0,%1,%2,%3},{%4,%5,%6,%7},{%8,%9},{%0,%1,%2,%3};"
        : "+f"(d[0]), "+f"(d[1]), "+f"(d[2]), "+f"(d[3])
        : "r"(a[0]), "r"(a[1]), "r"(a[2]), "r"(a[3]), "r"(b[0]), "r"(b[1]));
}

template<int EPI>
__global__ void __launch_bounds__(256, 2) gemm_bf(
    const bf16* __restrict__ A, const bf16* __restrict__ W,
    const float* __restrict__ bias, void* __restrict__ Cout,
    const float* __restrict__ ex, int N, int NP, int KP, int NKT)
{
    __shared__ __align__(1024) uint8_t sm[3 * 16384];
    uint32_t smb = (uint32_t)__cvta_generic_to_shared(sm);
    const int tid  = threadIdx.x;
    const int m0   = blockIdx.y * 128;
    const int n0   = blockIdx.x * 128;
    const int lane = tid & 31, wid = tid >> 5;
    const int g = lane >> 2, t4 = lane & 3;
    const int wm = wid & 1, wn = wid >> 1;

    // cp.async assignment: thread -> row r, chunks c, c+1 (c in {0,2})
    const int ra_ = tid >> 1;
    const int ca_ = (tid & 1) * 2;
    const int swr = (ra_ >> 1) & 3;

    auto issue = [&](int kt) {
        int stage = kt % 3;
        uint32_t base = smb + stage * 16384;
        int k0 = kt * 32;
        #pragma unroll
        for (int i = 0; i < 2; i++) {
            int c = ca_ + i;
            uint32_t d = base + ra_ * 64 + ((c ^ swr) * 16);
            cpa16(d, A + (size_t)(m0 + ra_) * KP + k0 + c * 8, 16);
        }
        int n = n0 + ra_;
        const bf16* wrow = W + (size_t)(n < N ? n : 0) * KP + k0;
        int sz = (n < N) ? 16 : 0;
        #pragma unroll
        for (int i = 0; i < 2; i++) {
            int c = ca_ + i;
            uint32_t d = base + 8192 + ra_ * 64 + ((c ^ swr) * 16);
            cpa16(d, wrow + c * 8, sz);
        }
        asm volatile("cp.async.commit_group;");
    };

    float acc[4][4][4];
    #pragma unroll
    for (int i = 0; i < 4; i++)
        #pragma unroll
        for (int j = 0; j < 4; j++)
            #pragma unroll
            for (int e = 0; e < 4; e++) acc[i][j][e] = 0.f;

    issue(0); issue(1);

    // ldmatrix address components
    const int raf  = lane & 15;
    const int kcf  = lane >> 4;
    const int swzA = (raf >> 1) & 3;
    const int rbf  = lane & 7;
    const int kbf  = (lane >> 3) & 1;
    const int swzB = (rbf >> 1) & 3;

    for (int kt = 0; kt < NKT; kt++) {
        if (kt + 2 < NKT) asm volatile("cp.async.wait_group 1;");
        else              asm volatile("cp.async.wait_group 0;");
        __syncthreads();
        if (kt + 2 < NKT) issue(kt + 2);

        uint32_t baseA = smb + (kt % 3) * 16384;
        uint32_t baseB = baseA + 8192;
        #pragma unroll
        for (int h = 0; h < 2; h++) {
            uint32_t aAddr = baseA + (wm * 64 + raf) * 64 + (((h * 2 + kcf) ^ swzA) * 16);
            uint32_t bAddr = baseB + (wn * 32 + rbf) * 64 + (((h * 2 + kbf) ^ swzB) * 16);
            uint32_t af[4][4], bfr[4][2];
            #pragma unroll
            for (int mt = 0; mt < 4; mt++)
                asm volatile("ldmatrix.sync.aligned.m8n8.x4.shared.b16 {%0,%1,%2,%3},[%4];"
                    : "=r"(af[mt][0]), "=r"(af[mt][1]), "=r"(af[mt][2]), "=r"(af[mt][3])
                    : "r"(aAddr + mt * 16 * 64));
            #pragma unroll
            for (int nt = 0; nt < 4; nt++)
                asm volatile("ldmatrix.sync.aligned.m8n8.x2.shared.b16 {%0,%1},[%2];"
                    : "=r"(bfr[nt][0]), "=r"(bfr[nt][1])
                    : "r"(bAddr + nt * 8 * 64));
            #pragma unroll
            for (int mt = 0; mt < 4; mt++)
                #pragma unroll
                for (int nt = 0; nt < 4; nt++)
                    mma_bf16(acc[mt][nt], af[mt], bfr[nt]);
        }
    }

    // epilogue  (c0,c1 = row g; c2,c3 = row g+8; cols t4*2, t4*2+1)
    #pragma unroll
    for (int mt = 0; mt < 4; mt++) {
        #pragma unroll
        for (int rr = 0; rr < 2; rr++) {
            int m = m0 + wm * 64 + mt * 16 + g + rr * 8;
            int b = m >> 16;
            int p = m & 65535;
            #pragma unroll
            for (int nt = 0; nt < 4; nt++) {
                int n = n0 + wn * 32 + nt * 8 + t4 * 2;
                float v0 = acc[mt][nt][rr * 2 + 0];
                float v1 = acc[mt][nt][rr * 2 + 1];
                if (EPI == 0) {
                    if (n < NP) {
                        if (bias) { if (n < N) v0 += bias[n]; if (n + 1 < N) v1 += bias[n + 1]; }
                        if (n     >= N) v0 = 0.f;
                        if (n + 1 >= N) v1 = 0.f;
                        ((__nv_bfloat162*)Cout)[((size_t)m * NP + n) >> 1] =
                            __floats2bfloat162_rn(v0, v1);
                    }
                } else if (EPI == 1) {
                    if (n < 180) {
                        v0 += bias[n] + ex[((size_t)b * 180 + n) * HW_ + p];
                        ((float*)Cout)[(size_t)m * 180 + n] = v0;
                    }
                    if (n + 1 < 180) {
                        v1 += bias[n + 1] + ex[((size_t)b * 180 + n + 1) * HW_ + p];
                        ((float*)Cout)[(size_t)m * 180 + n + 1] = v1;
                    }
                } else {
                    if (n < 180) {
                        v0 += ex[(size_t)m * 180 + n];
                        ((float*)Cout)[((size_t)b * 180 + n) * HW_ + p] = v0;
                    }
                    if (n + 1 < 180) {
                        v1 += ex[(size_t)m * 180 + n + 1];
                        ((float*)Cout)[((size_t)b * 180 + n + 1) * HW_ + p] = v1;
                    }
                }
            }
        }
    }
}

// ---------------------------------------------------------------------------
// Windowed attention: block = (window, head), thread = query token.
// Online softmax over 4 chunks of 16 keys. bf16 in/out, float2 smem k/v.
// ---------------------------------------------------------------------------
__global__ void __launch_bounds__(256) attn_kernel(
    const bf16* __restrict__ q, const bf16* __restrict__ kv,
    const float* __restrict__ rel_table, bf16* __restrict__ out)
{
    int head = blockIdx.y;
    int win  = blockIdx.x;
    int b  = win >> 8;
    int wl = win & 255;
    int base_h = (wl >> 4) * 16;
    int base_w = (wl & 15) * 16;

    __shared__ float ksf[64][32];
    __shared__ float vsf[64][32];
    __shared__ float rel_s[225];
    int tid = threadIdx.x;

    for (int i = tid; i < 225; i += 256) rel_s[i] = rel_table[i * 6 + head];

    for (int l = tid; l < 64 * 60; l += 256) {
        int m = l / 60; int r = l % 60; int s = r / 30; int e = r % 30;
        int t = head * 30 + e;
        int i2 = t / 90; int rr = t - i2 * 90; int j2 = rr / 45; int d = rr - j2 * 45;
        int py = base_h + ((m >> 3) << 1) + i2;
        int px = base_w + ((m & 7) << 1) + j2;
        size_t pix = (size_t)b * HW_ + py * 256 + px;
        float v = __bfloat162float(kv[pix * 90 + s * 45 + d]);
        if (s == 0) ksf[m][e] = v; else vsf[m][e] = v;
    }
    __syncthreads();

    int iy = tid >> 4, ix = tid & 15;
    size_t pixn = (size_t)b * HW_ + (base_h + iy) * 256 + base_w + ix;

    float2 q2[15];
    const __nv_bfloat162* qp = (const __nv_bfloat162*)(q + pixn * 192 + head * 30);
    #pragma unroll
    for (int e = 0; e < 15; e++) {
        __nv_bfloat162 h2 = qp[e];
        q2[e] = make_float2(__bfloat162float(h2.x), __bfloat162float(h2.y));
    }

    const float scale = 0.1825741858350554f;   // 30^-0.5
    int qy = iy >> 1, qx = ix >> 1;

    float runm = -1e30f, runs = 0.f;
    float acc[30];
    #pragma unroll
    for (int e = 0; e < 30; e++) acc[e] = 0.f;

    #pragma unroll
    for (int c0 = 0; c0 < 64; c0 += 16) {
        float lg[16];
        float cmax = -1e30f;
        #pragma unroll
        for (int j = 0; j < 16; j++) {
            int m = c0 + j;
            const float2* krow = (const float2*)ksf[m];
            float dot = 0.f;
            #pragma unroll
            for (int e = 0; e < 15; e++) {
                float2 k2 = krow[e];
                dot += q2[e].x * k2.x + q2[e].y * k2.y;
            }
            int dy = qy - (m >> 3) + 7;
            int dx = qx - (m & 7) + 7;
            float v = dot * scale + rel_s[dy * 15 + dx];
            lg[j] = v;
            cmax = fmaxf(cmax, v);
        }
        float newm = fmaxf(runm, cmax);
        float f = __expf(runm - newm);
        runs *= f;
        #pragma unroll
        for (int e = 0; e < 30; e++) acc[e] *= f;
        #pragma unroll
        for (int j = 0; j < 16; j++) {
            float p = __expf(lg[j] - newm);
            runs += p;
            const float2* vrow = (const float2*)vsf[c0 + j];
            #pragma unroll
            for (int e = 0; e < 15; e++) {
                float2 v2 = vrow[e];
                acc[2 * e]     += p * v2.x;
                acc[2 * e + 1] += p * v2.y;
            }
        }
        runm = newm;
    }
    float inv = 1.0f / runs;
    __nv_bfloat162* op = (__nv_bfloat162*)(out + pixn * 192 + head * 30);
    #pragma unroll
    for (int e = 0; e < 15; e++)
        op[e] = __floats2bfloat162_rn(acc[2 * e] * inv, acc[2 * e + 1] * inv);
}

// ---------------------------------------------------------------------------
// LN2 over pixel-major fp32 x1 + FiLM -> bf16 y2 (stride 192, pad zeros)
// ---------------------------------------------------------------------------
__global__ void __launch_bounds__(256) ln2_kernel(
    const float* __restrict__ x1, const float* __restrict__ lw,
    const float* __restrict__ lb, const float* __restrict__ kvf,
    bf16* __restrict__ out)
{
    int warp = threadIdx.x >> 5, lane = threadIdx.x & 31;
    size_t pix = (size_t)blockIdx.x * 8 + warp;
    int b = (int)(pix >> 16);
    const float* xp = x1 + pix * 180;

    float vals[6];
    float s = 0.f, ss = 0.f;
    #pragma unroll
    for (int i = 0; i < 6; i++) {
        int c = lane + i * 32;
        float v = (c < 180) ? xp[c] : 0.f;
        vals[i] = v; s += v; ss += v * v;
    }
    #pragma unroll
    for (int off = 16; off > 0; off >>= 1) {
        s  += __shfl_xor_sync(0xffffffffu, s,  off);
        ss += __shfl_xor_sync(0xffffffffu, ss, off);
    }
    float mean = s * (1.f / 180.f);
    float var  = ss * (1.f / 180.f) - mean * mean;
    float rstd = rsqrtf(var + 1e-5f);

    bf16* op = out + pix * 192;
    #pragma unroll
    for (int i = 0; i < 6; i++) {
        int c = lane + i * 32;
        int cc = (c < 180) ? c : 0;
        float v = (vals[i] - mean) * rstd * lw[cc] + lb[cc];
        v = v * kvf[b * 360 + cc] + kvf[b * 360 + 180 + cc];
        op[c] = __float2bfloat16(c < 180 ? v : 0.f);
    }
}

// ---------------------------------------------------------------------------
// Depthwise 3x3 + exact-GELU gate. u bf16 (stride 768) -> g bf16 (stride 384)
// ---------------------------------------------------------------------------
__global__ void __launch_bounds__(360) dwconv_kernel(
    const bf16* __restrict__ u, const float* __restrict__ wdw,
    bf16* __restrict__ g)
{
    const int CC = 45;
    __shared__ float tile[10][10][CC];

    int chunk = blockIdx.z & 7;
    int b     = blockIdx.z >> 3;
    int c0 = chunk * CC;
    int h0 = blockIdx.y * 8, w0 = blockIdx.x * 8;
    int ch = threadIdx.x;
    int xcol = threadIdx.y;
    int tid = threadIdx.y * CC + threadIdx.x;

    float v1[8];
    #pragma unroll
    for (int half = 0; half < 2; half++) {
        int cbase = half * 360 + c0;
        __syncthreads();
        for (int l = tid; l < 100 * CC; l += 360) {
            int cc = l % CC; int pp = l / CC;
            int py = h0 + pp / 10 - 1;
            int px = w0 + pp % 10 - 1;
            float v = 0.f;
            if (py >= 0 && py < 256 && px >= 0 && px < 256)
                v = __bfloat162float(u[((size_t)b * HW_ + py * 256 + px) * 768 + cbase + cc]);
            tile[pp / 10][pp % 10][cc] = v;
        }
        __syncthreads();
        float wreg[9];
        #pragma unroll
        for (int r = 0; r < 9; r++) wreg[r] = wdw[(size_t)(cbase + ch) * 9 + r];
        #pragma unroll
        for (int oy = 0; oy < 8; oy++) {
            float a = 0.f;
            #pragma unroll
            for (int ky = 0; ky < 3; ky++)
                #pragma unroll
                for (int kx = 0; kx < 3; kx++)
                    a += tile[oy + ky][xcol + kx][ch] * wreg[ky * 3 + kx];
            if (half == 0) {
                v1[oy] = a;
            } else {
                float g1 = v1[oy];
                float gl = 0.5f * g1 * (1.f + erff(g1 * 0.70710678118654752f));
                g[((size_t)b * HW_ + (h0 + oy) * 256 + w0 + xcol) * 384 + c0 + ch] =
                    __float2bfloat16(gl * a);
            }
        }
    }
    // pad ch 360..383 = 0 (chunk 7 blocks)
    if (chunk == 7) {
        for (int l = tid; l < 64 * 24; l += 360) {
            int p = l / 24, cp = 360 + l % 24;
            g[((size_t)b * HW_ + (h0 + p / 8) * 256 + w0 + (p & 7)) * 384 + cp] =
                __float2bfloat16(0.f);
        }
    }
}

// ---------------------------------------------------------------------------
// Launch sequence
// ---------------------------------------------------------------------------
extern "C" void kernel_launch(void* const* d_in, const int* in_sizes, int n_in,
                              void* d_out, int out_size)
{
    const float* x           = (const float*)d_in[0];
    const float* k_v         = (const float*)d_in[1];
    const float* ln1_w       = (const float*)d_in[2];
    const float* ln1_b       = (const float*)d_in[3];
    const float* ln2_w       = (const float*)d_in[4];
    const float* ln2_b       = (const float*)d_in[5];
    const float* w_kern_attn = (const float*)d_in[6];
    const float* rel_table   = (const float*)d_in[7];
    const float* w_kv        = (const float*)d_in[8];
    const float* b_kv        = (const float*)d_in[9];
    const float* w_q         = (const float*)d_in[10];
    const float* b_q         = (const float*)d_in[11];
    const float* w_proj      = (const float*)d_in[12];
    const float* b_proj      = (const float*)d_in[13];
    const float* w_kern_ffn  = (const float*)d_in[14];
    const float* w_pin       = (const float*)d_in[15];
    const float* w_dw        = (const float*)d_in[16];
    const float* w_pout      = (const float*)d_in[17];
    float* out = (float*)d_out;

    float *x1, *kvm, *kvf;
    bf16 *ymod, *qb, *kvb, *y2, *u, *gt, *wq, *wkv, *wproj, *wpin, *wpout;
    cudaGetSymbolAddress((void**)&ymod,  g_ymod);
    cudaGetSymbolAddress((void**)&qb,    g_qb);
    cudaGetSymbolAddress((void**)&kvb,   g_kvb);
    cudaGetSymbolAddress((void**)&x1,    g_x1);
    cudaGetSymbolAddress((void**)&y2,    g_y2);
    cudaGetSymbolAddress((void**)&u,     g_u);
    cudaGetSymbolAddress((void**)&gt,    g_gt);
    cudaGetSymbolAddress((void**)&kvm,   g_kvm);
    cudaGetSymbolAddress((void**)&kvf,   g_kvf);
    cudaGetSymbolAddress((void**)&wq,    g_wq);
    cudaGetSymbolAddress((void**)&wkv,   g_wkv);
    cudaGetSymbolAddress((void**)&wproj, g_wproj);
    cudaGetSymbolAddress((void**)&wpin,  g_wpin);
    cudaGetSymbolAddress((void**)&wpout, g_wpout);

    // weight conversions (tiny)
    wconv_kernel<<<(180 * 192 + 255) / 256, 256>>>(w_q,    wq,    180, 180, 192);
    wconv_kernel<<<( 90 * 192 + 255) / 256, 256>>>(w_kv,   wkv,    90, 180, 192);
    wconv_kernel<<<(180 * 192 + 255) / 256, 256>>>(w_proj, wproj, 180, 180, 192);
    wconv_kernel<<<(720 * 192 + 255) / 256, 256>>>(w_pin,  wpin,  720, 180, 192);
    wconv_kernel<<<(180 * 384 + 255) / 256, 256>>>(w_pout, wpout, 180, 360, 384);

    kvm_kernel<<<4, 256>>>(k_v, w_kern_attn, w_kern_ffn, kvm, kvf);
    ln1_kernel<<<dim3(2048, 4), 256>>>(x, ln1_w, ln1_b, kvm, ymod);

    gemm_bf<0><<<dim3(2, 2048), 256>>>(ymod, wq,  b_q,  qb,  nullptr, 180, 192, 192, 6);
    gemm_bf<0><<<dim3(1, 2048), 256>>>(ymod, wkv, b_kv, kvb, nullptr,  90,  90, 192, 6);

    attn_kernel<<<dim3(1024, 6), 256>>>(qb, kvb, rel_table, ymod);

    gemm_bf<1><<<dim3(2, 2048), 256>>>(ymod, wproj, b_proj, x1, x, 180, 180, 192, 6);

    ln2_kernel<<<32768, 256>>>(x1, ln2_w, ln2_b, kvf, y2);

    gemm_bf<0><<<dim3(6, 2048), 256>>>(y2, wpin, nullptr, u, nullptr, 720, 768, 192, 6);

    dwconv_kernel<<<dim3(32, 32, 32), dim3(45, 8)>>>(u, w_dw, gt);

    gemm_bf<2><<<dim3(2, 2048), 256>>>(gt, wpout, nullptr, out, x1, 180, 180, 384, 12);
}